// round 13
// baseline (speedup 1.0000x reference)
#include <cuda_runtime.h>
#include <cuda_bf16.h>
#include <cstdint>

// Volume rendering composite.
// Inputs: depth [N,192,1] f32, rgb [N,192,3] f32, sigma [N,192,1] f32
// Output (concat, f32): color [N,3], depth_out [N,1], acc_map [N,1], weights [N,192,1]
//
// One warp per TWO consecutive rays, software-pipelined:
//   LDG d/s(ray0) -> cp.async rgb0 (group A) -> cp.async d1,s1,rgb1 (group B)
//   -> process ray0 -> wait A, consume rgb0 -> wait B, LDS d1/s1 -> process ray1.
// The async engine streams ray1's 6KB while the warp computes ray0, so the
// exposed LDG window is paid once per two rays. All global traffic coalesced
// 128/64-bit; rgb consume is a compile-time component swizzle from smem.

#define NRAYS 65536
#define NSAMP 192
#define WPB   8
#define RGBF  (NSAMP * 3)        // 576
// per-warp smem floats: rgb0 [0,576) | rgb1 [576,1152) | d1 [1152,1344) | g1 [1344,1536)
#define WSLOT 1536

__device__ __forceinline__ float ex2_approx(float x) {
    float r; asm("ex2.approx.f32 %0, %1;" : "=f"(r) : "f"(x)); return r;
}
__device__ __forceinline__ float tanh_approx(float x) {
    float r; asm("tanh.approx.f32 %0, %1;" : "=f"(r) : "f"(x)); return r;
}
__device__ __forceinline__ float sigmoid_fast(float x) {
    return fmaf(0.5f, tanh_approx(0.5f * x), 0.5f);
}
__device__ __forceinline__ uint32_t smem_u32(const void* p) {
    uint32_t a;
    asm("{ .reg .u64 t; cvta.to.shared.u64 t, %1; cvt.u32.u64 %0, t; }"
        : "=r"(a) : "l"(p));
    return a;
}
__device__ __forceinline__ void cpa16(uint32_t dst, const void* src) {
    asm volatile("cp.async.cg.shared.global [%0], [%1], 16;\n" :: "r"(dst), "l"(src));
}
__device__ __forceinline__ void cpa8(uint32_t dst, const void* src) {
    asm volatile("cp.async.ca.shared.global [%0], [%1], 8;\n" :: "r"(dst), "l"(src));
}

// Full per-ray pipeline given register-resident depth/sigma and smem rgb row.
__device__ __forceinline__ void process_ray(
    int ray, int lane,
    float4 dA, float2 dB, float4 gA, float2 gB,
    const float* __restrict__ rr,      // smem rgb row for this ray
    float* __restrict__ out)
{
    const float BOARDER = 1e10f;
    const float EPS     = 1e-10f;
    const float LOG2E   = 1.4426950408889634f;
    const unsigned FULL = 0xffffffffu;

    // neighbor depths across lanes
    float ndA = __shfl_down_sync(FULL, dA.x, 1);
    const float bA = __shfl_sync(FULL, dB.x, 0);          // d[128]
    if (lane == 31) ndA = bA;
    const float ndB = __shfl_down_sync(FULL, dB.x, 1);    // d[128+2l+2]

    // chunk A: 4 survivals, warp product-scan
    const float eA0 = ex2_approx(-(fmaxf(gA.x, 0.f) * (dA.y - dA.x)) * LOG2E);
    const float eA1 = ex2_approx(-(fmaxf(gA.y, 0.f) * (dA.z - dA.y)) * LOG2E);
    const float eA2 = ex2_approx(-(fmaxf(gA.z, 0.f) * (dA.w - dA.z)) * LOG2E);
    const float eA3 = ex2_approx(-(fmaxf(gA.w, 0.f) * (ndA  - dA.w)) * LOG2E);
    const float sA0 = eA0 + EPS, sA1 = eA1 + EPS, sA2 = eA2 + EPS, sA3 = eA3 + EPS;

    float inclA = (sA0 * sA1) * (sA2 * sA3);
    #pragma unroll
    for (int off = 1; off < 32; off <<= 1) {
        const float v = __shfl_up_sync(FULL, inclA, off);
        if (lane >= off) inclA *= v;
    }
    float exclA = __shfl_up_sync(FULL, inclA, 1);
    if (lane == 0) exclA = 1.0f;

    float T = exclA;
    const float w0 = (1.0f - eA0) * T;  T *= sA0;
    const float w1 = (1.0f - eA1) * T;  T *= sA1;
    const float w2 = (1.0f - eA2) * T;  T *= sA2;
    const float w3 = (1.0f - eA3) * T;
    const float carry = __shfl_sync(FULL, inclA, 31);

    float dacc = fmaf(w0, dA.x, fmaf(w1, dA.y, fmaf(w2, dA.z, w3 * dA.w)));
    float aacc = (w0 + w1) + (w2 + w3);

    // chunk B: 2 survivals, scan seeded by carry
    const float eB0 = ex2_approx(-(fmaxf(gB.x, 0.f) * (dB.y - dB.x)) * LOG2E);
    const float delB1 = (lane == 31) ? BOARDER : (ndB - dB.y);
    const float eB1 = ex2_approx(-(fmaxf(gB.y, 0.f) * delB1) * LOG2E);
    const float sB0 = eB0 + EPS, sB1 = eB1 + EPS;

    float inclB = sB0 * sB1;
    #pragma unroll
    for (int off = 1; off < 32; off <<= 1) {
        const float v = __shfl_up_sync(FULL, inclB, off);
        if (lane >= off) inclB *= v;
    }
    float exclB = __shfl_up_sync(FULL, inclB, 1);
    if (lane == 0) exclB = 1.0f;

    const float TB  = carry * exclB;
    const float wB0 = (1.0f - eB0) * TB;
    const float wB1 = (1.0f - eB1) * (TB * sB0);

    dacc = fmaf(wB0, dB.x, fmaf(wB1, dB.y, dacc));
    aacc += wB0 + wB1;

    // weights: direct coalesced stores
    float* __restrict__ wbase = out + (size_t)NRAYS * 5 + (size_t)ray * NSAMP;
    __stcs((float4*)wbase + lane, make_float4(w0, w1, w2, w3));
    __stcs((float2*)(wbase + 128) + lane, make_float2(wB0, wB1));

    // rgb consume: lane reads its OWN samples (compile-time swizzle)
    const float4 rA0 = *(const float4*)(rr + 12 * lane);      // r0 g0 b0 r1
    const float4 rA1 = *(const float4*)(rr + 12 * lane + 4);  // g1 b1 r2 g2
    const float4 rA2 = *(const float4*)(rr + 12 * lane + 8);  // b2 r3 g3 b3
    const float2 rB0 = *(const float2*)(rr + 384 + 6 * lane);     // r0 g0
    const float2 rB1 = *(const float2*)(rr + 384 + 6 * lane + 2); // b0 r1
    const float2 rB2 = *(const float2*)(rr + 384 + 6 * lane + 4); // g1 b1

    float c0, c1, c2;
    c0 = fmaf(w0, sigmoid_fast(rA0.x),
         fmaf(w1, sigmoid_fast(rA0.w),
         fmaf(w2, sigmoid_fast(rA1.z),
              w3 * sigmoid_fast(rA2.y))));
    c1 = fmaf(w0, sigmoid_fast(rA0.y),
         fmaf(w1, sigmoid_fast(rA1.x),
         fmaf(w2, sigmoid_fast(rA1.w),
              w3 * sigmoid_fast(rA2.z))));
    c2 = fmaf(w0, sigmoid_fast(rA0.z),
         fmaf(w1, sigmoid_fast(rA1.y),
         fmaf(w2, sigmoid_fast(rA2.x),
              w3 * sigmoid_fast(rA2.w))));
    c0 = fmaf(wB0, sigmoid_fast(rB0.x), fmaf(wB1, sigmoid_fast(rB1.y), c0));
    c1 = fmaf(wB0, sigmoid_fast(rB0.y), fmaf(wB1, sigmoid_fast(rB2.x), c1));
    c2 = fmaf(wB0, sigmoid_fast(rB1.x), fmaf(wB1, sigmoid_fast(rB2.y), c2));

    // warp reduction + per-ray outputs
    #pragma unroll
    for (int off = 16; off > 0; off >>= 1) {
        c0   += __shfl_down_sync(FULL, c0,   off);
        c1   += __shfl_down_sync(FULL, c1,   off);
        c2   += __shfl_down_sync(FULL, c2,   off);
        dacc += __shfl_down_sync(FULL, dacc, off);
        aacc += __shfl_down_sync(FULL, aacc, off);
    }
    if (lane == 0) {
        out[3 * ray + 0] = c0;
        out[3 * ray + 1] = c1;
        out[3 * ray + 2] = c2;
        out[(size_t)NRAYS * 3 + ray] = dacc;
        out[(size_t)NRAYS * 4 + ray] = aacc;
    }
}

__global__ void __launch_bounds__(256, 4)
volrend_kernel(const float* __restrict__ depth,
               const float* __restrict__ rgb,
               const float* __restrict__ sigma,
               float* __restrict__ out)
{
    const int wid  = threadIdx.x >> 5;
    const int lane = threadIdx.x & 31;
    const int gw   = blockIdx.x * WPB + wid;
    const int r0   = 2 * gw;
    const int r1   = r0 + 1;

    __shared__ __align__(16) float spool[WPB][WSLOT];   // 48KB/block
    float* const wrow = spool[wid];
    const uint32_t wbase_s = smem_u32(wrow);

    // ---- 1) ray0 depth/sigma LDGs first (critical path) ----
    const float* d0b = depth + (size_t)r0 * NSAMP;
    const float* g0b = sigma + (size_t)r0 * NSAMP;
    const float4 dA0 = __ldcs((const float4*)d0b + lane);
    const float2 dB0 = __ldcs((const float2*)(d0b + 128) + lane);
    const float4 gA0 = __ldcs((const float4*)g0b + lane);
    const float2 gB0 = __ldcs((const float2*)(g0b + 128) + lane);

    // ---- 2) group A: rgb0 -> smem ----
    {
        const char* src = (const char*)(rgb + (size_t)r0 * RGBF);
        #pragma unroll
        for (int t = 0; t < 4; ++t)
            cpa16(wbase_s + (32 * t + lane) * 16, src + (32 * t + lane) * 16);
        cpa8(wbase_s + 2048 + lane * 8, src + 2048 + lane * 8);
    }
    asm volatile("cp.async.commit_group;\n");

    // ---- 3) group B: d1, g1, rgb1 -> smem ----
    {
        const char* dsrc = (const char*)(depth + (size_t)r1 * NSAMP);
        const char* gsrc = (const char*)(sigma + (size_t)r1 * NSAMP);
        const uint32_t d1s = wbase_s + 1152 * 4;
        const uint32_t g1s = wbase_s + 1344 * 4;
        cpa16(d1s + lane * 16, dsrc + lane * 16);              // floats 0..127
        if (lane < 16) cpa16(d1s + 512 + lane * 16, dsrc + 512 + lane * 16);
        cpa16(g1s + lane * 16, gsrc + lane * 16);
        if (lane < 16) cpa16(g1s + 512 + lane * 16, gsrc + 512 + lane * 16);

        const char* rsrc = (const char*)(rgb + (size_t)r1 * RGBF);
        const uint32_t r1s = wbase_s + 576 * 4;
        #pragma unroll
        for (int t = 0; t < 4; ++t)
            cpa16(r1s + (32 * t + lane) * 16, rsrc + (32 * t + lane) * 16);
        cpa8(r1s + 2048 + lane * 8, rsrc + 2048 + lane * 8);
    }
    asm volatile("cp.async.commit_group;\n");

    // ---- 4) process ray0 up to rgb: need group A done ----
    asm volatile("cp.async.wait_group 1;\n" ::: "memory");
    __syncwarp();
    process_ray(r0, lane, dA0, dB0, gA0, gB0, wrow, out);

    // ---- 5) ray1: everything already in smem ----
    asm volatile("cp.async.wait_group 0;\n" ::: "memory");
    __syncwarp();
    const float* d1p = wrow + 1152;
    const float* g1p = wrow + 1344;
    const float4 dA1 = *(const float4*)(d1p + 4 * lane);
    const float2 dB1 = *(const float2*)(d1p + 128 + 2 * lane);
    const float4 gA1 = *(const float4*)(g1p + 4 * lane);
    const float2 gB1 = *(const float2*)(g1p + 128 + 2 * lane);
    process_ray(r1, lane, dA1, dB1, gA1, gB1, wrow + 576, out);
}

extern "C" void kernel_launch(void* const* d_in, const int* in_sizes, int n_in,
                              void* d_out, int out_size)
{
    const float* depth = (const float*)d_in[0];
    const float* rgb   = (const float*)d_in[1];
    const float* sigma = (const float*)d_in[2];
    float* out = (float*)d_out;

    const int threads = 32 * WPB;                    // 256
    const int blocks  = NRAYS / (2 * WPB);           // 4096 (2 rays per warp)
    volrend_kernel<<<blocks, threads>>>(depth, rgb, sigma, out);
}

// round 14
// speedup vs baseline: 1.0020x; 1.0020x over previous
#include <cuda_runtime.h>
#include <cuda_bf16.h>
#include <cstdint>

// Volume rendering composite.
// Inputs: depth [N,192,1] f32, rgb [N,192,3] f32, sigma [N,192,1] f32
// Output (concat, f32): color [N,3], depth_out [N,1], acc_map [N,1], weights [N,192,1]
//
// One warp per ray; ALL input traffic via cp.async (register-free MLP):
//   group 0: depth+sigma -> smem   (critical path, waited first)
//   group 1: rgb -> smem           (streams behind the scan)
// Warp holds no in-flight load registers -> low reg count -> high occupancy
// AND high memory-level parallelism simultaneously.
// Weights: direct coalesced STG.128/STG.64 from registers.
// rgb consume: compile-time component swizzle from smem.

#define NRAYS 65536
#define NSAMP 192
#define WPB   8
#define RGBF  (NSAMP * 3)        // 576
// per-warp smem floats: rgb [0,576) | d [576,768) | g [768,960)
#define WSLOT 960                // 3840 B/warp, 30720 B/block

__device__ __forceinline__ float ex2_approx(float x) {
    float r; asm("ex2.approx.f32 %0, %1;" : "=f"(r) : "f"(x)); return r;
}
__device__ __forceinline__ float tanh_approx(float x) {
    float r; asm("tanh.approx.f32 %0, %1;" : "=f"(r) : "f"(x)); return r;
}
// sigmoid(x) = 0.5*tanh(x/2) + 0.5  (one MUFU op)
__device__ __forceinline__ float sigmoid_fast(float x) {
    return fmaf(0.5f, tanh_approx(0.5f * x), 0.5f);
}
__device__ __forceinline__ uint32_t smem_u32(const void* p) {
    uint32_t a;
    asm("{ .reg .u64 t; cvta.to.shared.u64 t, %1; cvt.u32.u64 %0, t; }"
        : "=r"(a) : "l"(p));
    return a;
}
__device__ __forceinline__ void cpa16(uint32_t dst, const void* src) {
    asm volatile("cp.async.cg.shared.global [%0], [%1], 16;\n" :: "r"(dst), "l"(src));
}
__device__ __forceinline__ void cpa8(uint32_t dst, const void* src) {
    asm volatile("cp.async.ca.shared.global [%0], [%1], 8;\n" :: "r"(dst), "l"(src));
}

__global__ void __launch_bounds__(256, 7)
volrend_kernel(const float* __restrict__ depth,
               const float* __restrict__ rgb,
               const float* __restrict__ sigma,
               float* __restrict__ out)
{
    const int wid  = threadIdx.x >> 5;
    const int lane = threadIdx.x & 31;
    const int ray  = blockIdx.x * WPB + wid;

    __shared__ __align__(16) float spool[WPB][WSLOT];   // 30.7 KB/block
    float* const wrow = spool[wid];
    const uint32_t sbase = smem_u32(wrow);
    const uint32_t s_rgb = sbase;
    const uint32_t s_d   = sbase + 576 * 4;
    const uint32_t s_g   = sbase + 768 * 4;

    const float BOARDER = 1e10f;
    const float EPS     = 1e-10f;
    const float LOG2E   = 1.4426950408889634f;
    const unsigned FULL = 0xffffffffu;

    // ---- 1) group 0: depth + sigma -> smem (critical path) ----
    {
        const char* dsrc = (const char*)(depth + (size_t)ray * NSAMP);
        const char* gsrc = (const char*)(sigma + (size_t)ray * NSAMP);
        cpa16(s_d + lane * 16, dsrc + lane * 16);                   // 512 B
        cpa16(s_g + lane * 16, gsrc + lane * 16);
        if (lane < 16) {
            cpa16(s_d + 512 + lane * 16, dsrc + 512 + lane * 16);   // 256 B
            cpa16(s_g + 512 + lane * 16, gsrc + 512 + lane * 16);
        }
    }
    asm volatile("cp.async.commit_group;\n");

    // ---- 2) group 1: rgb -> smem (streams behind the scan) ----
    {
        const char* rsrc = (const char*)(rgb + (size_t)ray * RGBF);
        #pragma unroll
        for (int t = 0; t < 4; ++t)
            cpa16(s_rgb + (32 * t + lane) * 16, rsrc + (32 * t + lane) * 16);
        cpa8(s_rgb + 2048 + lane * 8, rsrc + 2048 + lane * 8);
    }
    asm volatile("cp.async.commit_group;\n");

    // ---- 3) wait for depth+sigma, read from smem ----
    asm volatile("cp.async.wait_group 1;\n" ::: "memory");
    __syncwarp();
    const float* dp = wrow + 576;
    const float* gp = wrow + 768;
    const float4 dA = *(const float4*)(dp + 4 * lane);          // 4l..4l+3
    const float2 dB = *(const float2*)(dp + 128 + 2 * lane);    // 128+2l..+1
    const float4 gA = *(const float4*)(gp + 4 * lane);
    const float2 gB = *(const float2*)(gp + 128 + 2 * lane);

    // neighbor depths across lanes
    float ndA = __shfl_down_sync(FULL, dA.x, 1);
    const float bA = __shfl_sync(FULL, dB.x, 0);       // d[128]
    if (lane == 31) ndA = bA;
    const float ndB = __shfl_down_sync(FULL, dB.x, 1); // d[128+2l+2]

    // ---- 4) chunk A: 4 survivals, warp product-scan ----
    const float eA0 = ex2_approx(-(fmaxf(gA.x, 0.f) * (dA.y - dA.x)) * LOG2E);
    const float eA1 = ex2_approx(-(fmaxf(gA.y, 0.f) * (dA.z - dA.y)) * LOG2E);
    const float eA2 = ex2_approx(-(fmaxf(gA.z, 0.f) * (dA.w - dA.z)) * LOG2E);
    const float eA3 = ex2_approx(-(fmaxf(gA.w, 0.f) * (ndA  - dA.w)) * LOG2E);
    const float sA0 = eA0 + EPS, sA1 = eA1 + EPS, sA2 = eA2 + EPS, sA3 = eA3 + EPS;

    float inclA = (sA0 * sA1) * (sA2 * sA3);
    #pragma unroll
    for (int off = 1; off < 32; off <<= 1) {
        const float v = __shfl_up_sync(FULL, inclA, off);
        if (lane >= off) inclA *= v;
    }
    float exclA = __shfl_up_sync(FULL, inclA, 1);
    if (lane == 0) exclA = 1.0f;

    float T = exclA;
    const float w0 = (1.0f - eA0) * T;  T *= sA0;
    const float w1 = (1.0f - eA1) * T;  T *= sA1;
    const float w2 = (1.0f - eA2) * T;  T *= sA2;
    const float w3 = (1.0f - eA3) * T;
    const float carry = __shfl_sync(FULL, inclA, 31);

    float dacc = fmaf(w0, dA.x, fmaf(w1, dA.y, fmaf(w2, dA.z, w3 * dA.w)));
    float aacc = (w0 + w1) + (w2 + w3);

    // ---- 5) chunk B: 2 survivals, scan seeded by carry ----
    const float eB0 = ex2_approx(-(fmaxf(gB.x, 0.f) * (dB.y - dB.x)) * LOG2E);
    const float delB1 = (lane == 31) ? BOARDER : (ndB - dB.y);
    const float eB1 = ex2_approx(-(fmaxf(gB.y, 0.f) * delB1) * LOG2E);
    const float sB0 = eB0 + EPS, sB1 = eB1 + EPS;

    float inclB = sB0 * sB1;
    #pragma unroll
    for (int off = 1; off < 32; off <<= 1) {
        const float v = __shfl_up_sync(FULL, inclB, off);
        if (lane >= off) inclB *= v;
    }
    float exclB = __shfl_up_sync(FULL, inclB, 1);
    if (lane == 0) exclB = 1.0f;

    const float TB  = carry * exclB;
    const float wB0 = (1.0f - eB0) * TB;
    const float wB1 = (1.0f - eB1) * (TB * sB0);

    dacc = fmaf(wB0, dB.x, fmaf(wB1, dB.y, dacc));
    aacc += wB0 + wB1;

    // ---- 6) weights: direct coalesced stores ----
    float* __restrict__ wbase = out + (size_t)NRAYS * 5 + (size_t)ray * NSAMP;
    __stcs((float4*)wbase + lane, make_float4(w0, w1, w2, w3));
    __stcs((float2*)(wbase + 128) + lane, make_float2(wB0, wB1));

    // ---- 7) rgb consume (compile-time swizzle from smem) ----
    asm volatile("cp.async.wait_group 0;\n" ::: "memory");
    __syncwarp();

    const float* rr = wrow;
    const float4 rA0 = *(const float4*)(rr + 12 * lane);      // r0 g0 b0 r1
    const float4 rA1 = *(const float4*)(rr + 12 * lane + 4);  // g1 b1 r2 g2
    const float4 rA2 = *(const float4*)(rr + 12 * lane + 8);  // b2 r3 g3 b3
    const float2 rB0 = *(const float2*)(rr + 384 + 6 * lane);     // r0 g0
    const float2 rB1 = *(const float2*)(rr + 384 + 6 * lane + 2); // b0 r1
    const float2 rB2 = *(const float2*)(rr + 384 + 6 * lane + 4); // g1 b1

    float c0, c1, c2;
    c0 = fmaf(w0, sigmoid_fast(rA0.x),
         fmaf(w1, sigmoid_fast(rA0.w),
         fmaf(w2, sigmoid_fast(rA1.z),
              w3 * sigmoid_fast(rA2.y))));
    c1 = fmaf(w0, sigmoid_fast(rA0.y),
         fmaf(w1, sigmoid_fast(rA1.x),
         fmaf(w2, sigmoid_fast(rA1.w),
              w3 * sigmoid_fast(rA2.z))));
    c2 = fmaf(w0, sigmoid_fast(rA0.z),
         fmaf(w1, sigmoid_fast(rA1.y),
         fmaf(w2, sigmoid_fast(rA2.x),
              w3 * sigmoid_fast(rA2.w))));
    c0 = fmaf(wB0, sigmoid_fast(rB0.x), fmaf(wB1, sigmoid_fast(rB1.y), c0));
    c1 = fmaf(wB0, sigmoid_fast(rB0.y), fmaf(wB1, sigmoid_fast(rB2.x), c1));
    c2 = fmaf(wB0, sigmoid_fast(rB1.x), fmaf(wB1, sigmoid_fast(rB2.y), c2));

    // ---- 8) warp reduction + per-ray outputs ----
    #pragma unroll
    for (int off = 16; off > 0; off >>= 1) {
        c0   += __shfl_down_sync(FULL, c0,   off);
        c1   += __shfl_down_sync(FULL, c1,   off);
        c2   += __shfl_down_sync(FULL, c2,   off);
        dacc += __shfl_down_sync(FULL, dacc, off);
        aacc += __shfl_down_sync(FULL, aacc, off);
    }
    if (lane == 0) {
        out[3 * ray + 0] = c0;
        out[3 * ray + 1] = c1;
        out[3 * ray + 2] = c2;
        out[(size_t)NRAYS * 3 + ray] = dacc;
        out[(size_t)NRAYS * 4 + ray] = aacc;
    }
}

extern "C" void kernel_launch(void* const* d_in, const int* in_sizes, int n_in,
                              void* d_out, int out_size)
{
    const float* depth = (const float*)d_in[0];
    const float* rgb   = (const float*)d_in[1];
    const float* sigma = (const float*)d_in[2];
    float* out = (float*)d_out;

    const int threads = 32 * WPB;               // 256
    const int blocks  = NRAYS / WPB;            // 8192
    volrend_kernel<<<blocks, threads>>>(depth, rgb, sigma, out);
}

// round 15
// speedup vs baseline: 1.0294x; 1.0274x over previous
#include <cuda_runtime.h>
#include <cuda_bf16.h>
#include <cstdint>

// Volume rendering composite.
// Inputs: depth [N,192,1] f32, rgb [N,192,3] f32, sigma [N,192,1] f32
// Output (concat, f32): color [N,3], depth_out [N,1], acc_map [N,1], weights [N,192,1]
//
// One warp per ray (R10 structure — best measured):
//  - rgb (60% of read bytes) prefetched FIRST via cp.async.cg into per-warp
//    smem: traffic overlaps the scan phase; no registers held; L1 bypassed.
//  - depth/sigma: direct LDG.128/LDG.64 into registers (critical path stays
//    on the lowest-latency path).
//  - transmittance: 2 chained 5-step warp scans.
//  - weights: direct coalesced STG.128 + STG.64 from registers.
//  - rgb consume: compile-time component swizzle from smem.

#define NRAYS 65536
#define NSAMP 192
#define WPB   8
#define RGBF  (NSAMP * 3)   // 576 floats per ray

__device__ __forceinline__ float ex2_approx(float x) {
    float r; asm("ex2.approx.f32 %0, %1;" : "=f"(r) : "f"(x)); return r;
}
__device__ __forceinline__ float tanh_approx(float x) {
    float r; asm("tanh.approx.f32 %0, %1;" : "=f"(r) : "f"(x)); return r;
}
// sigmoid(x) = 0.5*tanh(x/2) + 0.5  (one MUFU op)
__device__ __forceinline__ float sigmoid_fast(float x) {
    return fmaf(0.5f, tanh_approx(0.5f * x), 0.5f);
}
__device__ __forceinline__ uint32_t smem_u32(const void* p) {
    uint32_t a;
    asm("{ .reg .u64 t; cvta.to.shared.u64 t, %1; cvt.u32.u64 %0, t; }"
        : "=r"(a) : "l"(p));
    return a;
}

__global__ void __launch_bounds__(256, 6)
volrend_kernel(const float* __restrict__ depth,
               const float* __restrict__ rgb,
               const float* __restrict__ sigma,
               float* __restrict__ out)
{
    const int wid  = threadIdx.x >> 5;
    const int lane = threadIdx.x & 31;
    const int ray  = blockIdx.x * WPB + wid;

    __shared__ __align__(16) float srgb[WPB][RGBF];   // 18.4 KB/block

    const float BOARDER = 1e10f;
    const float EPS     = 1e-10f;
    const float NLOG2E  = -1.4426950408889634f;
    const unsigned FULL = 0xffffffffu;

    // ---- 1) rgb prefetch: cp.async.cg, issued before ANY compute ----
    const char* rsrc = (const char*)(rgb + (size_t)ray * RGBF);
    const uint32_t rdst = smem_u32(&srgb[wid][0]);
    #pragma unroll
    for (int t = 0; t < 4; ++t) {
        asm volatile("cp.async.cg.shared.global [%0], [%1], 16;\n" ::
                     "r"(rdst + (32 * t + lane) * 16),
                     "l"(rsrc + (32 * t + lane) * 16));
    }
    // tail 256B: 16 lanes x 16B, .cg (no L1 pollution)
    if (lane < 16) {
        asm volatile("cp.async.cg.shared.global [%0], [%1], 16;\n" ::
                     "r"(rdst + 2048 + lane * 16),
                     "l"(rsrc + 2048 + lane * 16));
    }
    asm volatile("cp.async.commit_group;\n");

    // ---- 2) depth/sigma loads (coalesced 128/64-bit, straight to regs) ----
    const float* dbase = depth + (size_t)ray * NSAMP;
    const float* gbase = sigma + (size_t)ray * NSAMP;
    const float4 dA = __ldcs((const float4*)dbase + lane);          // 4l..4l+3
    const float2 dB = __ldcs((const float2*)(dbase + 128) + lane);  // 128+2l..+1
    const float4 gA = __ldcs((const float4*)gbase + lane);
    const float2 gB = __ldcs((const float2*)(gbase + 128) + lane);

    // next-sample depths across lane boundaries
    float ndA = __shfl_down_sync(FULL, dA.x, 1);
    const float bA = __shfl_sync(FULL, dB.x, 0);       // d[128]
    if (lane == 31) ndA = bA;
    const float ndB = __shfl_down_sync(FULL, dB.x, 1); // d[128+2l+2]

    // ---- 3) chunk A: 4 survivals, warp product-scan ----
    // fold -log2e into the relu'd sigma: e = ex2(gs * delta)
    const float gsA0 = fmaxf(gA.x, 0.f) * NLOG2E;
    const float gsA1 = fmaxf(gA.y, 0.f) * NLOG2E;
    const float gsA2 = fmaxf(gA.z, 0.f) * NLOG2E;
    const float gsA3 = fmaxf(gA.w, 0.f) * NLOG2E;
    const float eA0 = ex2_approx(gsA0 * (dA.y - dA.x));
    const float eA1 = ex2_approx(gsA1 * (dA.z - dA.y));
    const float eA2 = ex2_approx(gsA2 * (dA.w - dA.z));
    const float eA3 = ex2_approx(gsA3 * (ndA  - dA.w));
    const float sA0 = eA0 + EPS, sA1 = eA1 + EPS, sA2 = eA2 + EPS, sA3 = eA3 + EPS;

    float inclA = (sA0 * sA1) * (sA2 * sA3);
    #pragma unroll
    for (int off = 1; off < 32; off <<= 1) {
        const float v = __shfl_up_sync(FULL, inclA, off);
        if (lane >= off) inclA *= v;
    }
    float exclA = __shfl_up_sync(FULL, inclA, 1);
    if (lane == 0) exclA = 1.0f;

    float T = exclA;
    const float w0 = (1.0f - eA0) * T;  T *= sA0;
    const float w1 = (1.0f - eA1) * T;  T *= sA1;
    const float w2 = (1.0f - eA2) * T;  T *= sA2;
    const float w3 = (1.0f - eA3) * T;
    const float carry = __shfl_sync(FULL, inclA, 31);

    float dacc = fmaf(w0, dA.x, fmaf(w1, dA.y, fmaf(w2, dA.z, w3 * dA.w)));
    float aacc = (w0 + w1) + (w2 + w3);

    // ---- 4) chunk B: 2 survivals, scan seeded by carry ----
    const float gsB0 = fmaxf(gB.x, 0.f) * NLOG2E;
    const float gsB1 = fmaxf(gB.y, 0.f) * NLOG2E;
    const float eB0 = ex2_approx(gsB0 * (dB.y - dB.x));
    const float delB1 = (lane == 31) ? BOARDER : (ndB - dB.y);
    const float eB1 = ex2_approx(gsB1 * delB1);
    const float sB0 = eB0 + EPS, sB1 = eB1 + EPS;

    float inclB = sB0 * sB1;
    #pragma unroll
    for (int off = 1; off < 32; off <<= 1) {
        const float v = __shfl_up_sync(FULL, inclB, off);
        if (lane >= off) inclB *= v;
    }
    float exclB = __shfl_up_sync(FULL, inclB, 1);
    if (lane == 0) exclB = 1.0f;

    const float TB  = carry * exclB;
    const float wB0 = (1.0f - eB0) * TB;
    const float wB1 = (1.0f - eB1) * (TB * sB0);

    dacc = fmaf(wB0, dB.x, fmaf(wB1, dB.y, dacc));
    aacc += wB0 + wB1;

    // ---- 5) weights: direct coalesced stores ----
    float* __restrict__ wbase = out + (size_t)NRAYS * 5 + (size_t)ray * NSAMP;
    __stcs((float4*)wbase + lane, make_float4(w0, w1, w2, w3));
    __stcs((float2*)(wbase + 128) + lane, make_float2(wB0, wB1));

    // ---- 6) rgb consume: lane reads its OWN samples from smem ----
    asm volatile("cp.async.wait_group 0;\n" ::: "memory");
    __syncwarp();

    const float* rr = &srgb[wid][0];
    // samples 4l..4l+3 -> floats 12l..12l+11 (16B aligned)
    const float4 rA0 = *(const float4*)(rr + 12 * lane);      // r0 g0 b0 r1
    const float4 rA1 = *(const float4*)(rr + 12 * lane + 4);  // g1 b1 r2 g2
    const float4 rA2 = *(const float4*)(rr + 12 * lane + 8);  // b2 r3 g3 b3
    // samples 128+2l, 128+2l+1 -> floats 384+6l..+5 (8B aligned)
    const float2 rB0 = *(const float2*)(rr + 384 + 6 * lane);     // r0 g0
    const float2 rB1 = *(const float2*)(rr + 384 + 6 * lane + 2); // b0 r1
    const float2 rB2 = *(const float2*)(rr + 384 + 6 * lane + 4); // g1 b1

    float c0, c1, c2;
    c0 = fmaf(w0, sigmoid_fast(rA0.x),
         fmaf(w1, sigmoid_fast(rA0.w),
         fmaf(w2, sigmoid_fast(rA1.z),
              w3 * sigmoid_fast(rA2.y))));
    c1 = fmaf(w0, sigmoid_fast(rA0.y),
         fmaf(w1, sigmoid_fast(rA1.x),
         fmaf(w2, sigmoid_fast(rA1.w),
              w3 * sigmoid_fast(rA2.z))));
    c2 = fmaf(w0, sigmoid_fast(rA0.z),
         fmaf(w1, sigmoid_fast(rA1.y),
         fmaf(w2, sigmoid_fast(rA2.x),
              w3 * sigmoid_fast(rA2.w))));
    c0 = fmaf(wB0, sigmoid_fast(rB0.x), fmaf(wB1, sigmoid_fast(rB1.y), c0));
    c1 = fmaf(wB0, sigmoid_fast(rB0.y), fmaf(wB1, sigmoid_fast(rB2.x), c1));
    c2 = fmaf(wB0, sigmoid_fast(rB1.x), fmaf(wB1, sigmoid_fast(rB2.y), c2));

    // ---- 7) warp reduction + per-ray outputs ----
    #pragma unroll
    for (int off = 16; off > 0; off >>= 1) {
        c0   += __shfl_down_sync(FULL, c0,   off);
        c1   += __shfl_down_sync(FULL, c1,   off);
        c2   += __shfl_down_sync(FULL, c2,   off);
        dacc += __shfl_down_sync(FULL, dacc, off);
        aacc += __shfl_down_sync(FULL, aacc, off);
    }
    if (lane == 0) {
        out[3 * ray + 0] = c0;
        out[3 * ray + 1] = c1;
        out[3 * ray + 2] = c2;
        out[(size_t)NRAYS * 3 + ray] = dacc;
        out[(size_t)NRAYS * 4 + ray] = aacc;
    }
}

extern "C" void kernel_launch(void* const* d_in, const int* in_sizes, int n_in,
                              void* d_out, int out_size)
{
    const float* depth = (const float*)d_in[0];
    const float* rgb   = (const float*)d_in[1];
    const float* sigma = (const float*)d_in[2];
    float* out = (float*)d_out;

    const int threads = 32 * WPB;               // 256
    const int blocks  = NRAYS / WPB;            // 8192
    volrend_kernel<<<blocks, threads>>>(depth, rgb, sigma, out);
}

// round 16
// speedup vs baseline: 1.0357x; 1.0061x over previous
#include <cuda_runtime.h>
#include <cuda_bf16.h>
#include <cstdint>

// Volume rendering composite.
// Inputs: depth [N,192,1] f32, rgb [N,192,3] f32, sigma [N,192,1] f32
// Output (concat, f32): color [N,3], depth_out [N,1], acc_map [N,1], weights [N,192,1]
//
// One warp per ray (R10/R14 structure — best measured):
//  - rgb (60% of read bytes) prefetched FIRST via cp.async.cg into per-warp
//    smem: traffic overlaps the scan phase; no registers held; L1 bypassed.
//  - depth/sigma: direct LDG.128/LDG.64 into registers (critical path stays
//    on the lowest-latency path).
//  - transmittance: 2 chained 5-step warp scans.
//  - weights: direct coalesced STG.128 + STG.64 from registers.
//  - rgb consume: compile-time component swizzle from smem.
//  - THIS ROUND'S single variable: 36-reg cap (launch_bounds 256,7) -> 56
//    warps/SM theoretical, testing the unmeasured midpoint of the
//    occupancy-vs-LDG-batching frontier (40 regs good, 32 regs bad).

#define NRAYS 65536
#define NSAMP 192
#define WPB   8
#define RGBF  (NSAMP * 3)   // 576 floats per ray

__device__ __forceinline__ float ex2_approx(float x) {
    float r; asm("ex2.approx.f32 %0, %1;" : "=f"(r) : "f"(x)); return r;
}
__device__ __forceinline__ float tanh_approx(float x) {
    float r; asm("tanh.approx.f32 %0, %1;" : "=f"(r) : "f"(x)); return r;
}
// sigmoid(x) = 0.5*tanh(x/2) + 0.5  (one MUFU op)
__device__ __forceinline__ float sigmoid_fast(float x) {
    return fmaf(0.5f, tanh_approx(0.5f * x), 0.5f);
}
__device__ __forceinline__ uint32_t smem_u32(const void* p) {
    uint32_t a;
    asm("{ .reg .u64 t; cvta.to.shared.u64 t, %1; cvt.u32.u64 %0, t; }"
        : "=r"(a) : "l"(p));
    return a;
}

__global__ void __launch_bounds__(256, 7)
volrend_kernel(const float* __restrict__ depth,
               const float* __restrict__ rgb,
               const float* __restrict__ sigma,
               float* __restrict__ out)
{
    const int wid  = threadIdx.x >> 5;
    const int lane = threadIdx.x & 31;
    const int ray  = blockIdx.x * WPB + wid;

    __shared__ __align__(16) float srgb[WPB][RGBF];   // 18.4 KB/block

    const float BOARDER = 1e10f;
    const float EPS     = 1e-10f;
    const float NLOG2E  = -1.4426950408889634f;
    const unsigned FULL = 0xffffffffu;

    // ---- 1) rgb prefetch: cp.async.cg, issued before ANY compute ----
    const char* rsrc = (const char*)(rgb + (size_t)ray * RGBF);
    const uint32_t rdst = smem_u32(&srgb[wid][0]);
    #pragma unroll
    for (int t = 0; t < 4; ++t) {
        asm volatile("cp.async.cg.shared.global [%0], [%1], 16;\n" ::
                     "r"(rdst + (32 * t + lane) * 16),
                     "l"(rsrc + (32 * t + lane) * 16));
    }
    // tail 256B: 16 lanes x 16B, .cg (no L1 pollution)
    if (lane < 16) {
        asm volatile("cp.async.cg.shared.global [%0], [%1], 16;\n" ::
                     "r"(rdst + 2048 + lane * 16),
                     "l"(rsrc + 2048 + lane * 16));
    }
    asm volatile("cp.async.commit_group;\n");

    // ---- 2) depth/sigma loads (coalesced 128/64-bit, straight to regs) ----
    const float* dbase = depth + (size_t)ray * NSAMP;
    const float* gbase = sigma + (size_t)ray * NSAMP;
    const float4 dA = __ldcs((const float4*)dbase + lane);          // 4l..4l+3
    const float2 dB = __ldcs((const float2*)(dbase + 128) + lane);  // 128+2l..+1
    const float4 gA = __ldcs((const float4*)gbase + lane);
    const float2 gB = __ldcs((const float2*)(gbase + 128) + lane);

    // next-sample depths across lane boundaries
    float ndA = __shfl_down_sync(FULL, dA.x, 1);
    const float bA = __shfl_sync(FULL, dB.x, 0);       // d[128]
    if (lane == 31) ndA = bA;
    const float ndB = __shfl_down_sync(FULL, dB.x, 1); // d[128+2l+2]

    // ---- 3) chunk A: 4 survivals, warp product-scan ----
    // fold -log2e into the relu'd sigma: e = ex2(gs * delta)
    const float gsA0 = fmaxf(gA.x, 0.f) * NLOG2E;
    const float gsA1 = fmaxf(gA.y, 0.f) * NLOG2E;
    const float gsA2 = fmaxf(gA.z, 0.f) * NLOG2E;
    const float gsA3 = fmaxf(gA.w, 0.f) * NLOG2E;
    const float eA0 = ex2_approx(gsA0 * (dA.y - dA.x));
    const float eA1 = ex2_approx(gsA1 * (dA.z - dA.y));
    const float eA2 = ex2_approx(gsA2 * (dA.w - dA.z));
    const float eA3 = ex2_approx(gsA3 * (ndA  - dA.w));
    const float sA0 = eA0 + EPS, sA1 = eA1 + EPS, sA2 = eA2 + EPS, sA3 = eA3 + EPS;

    float inclA = (sA0 * sA1) * (sA2 * sA3);
    #pragma unroll
    for (int off = 1; off < 32; off <<= 1) {
        const float v = __shfl_up_sync(FULL, inclA, off);
        if (lane >= off) inclA *= v;
    }
    float exclA = __shfl_up_sync(FULL, inclA, 1);
    if (lane == 0) exclA = 1.0f;

    float T = exclA;
    const float w0 = (1.0f - eA0) * T;  T *= sA0;
    const float w1 = (1.0f - eA1) * T;  T *= sA1;
    const float w2 = (1.0f - eA2) * T;  T *= sA2;
    const float w3 = (1.0f - eA3) * T;
    const float carry = __shfl_sync(FULL, inclA, 31);

    float dacc = fmaf(w0, dA.x, fmaf(w1, dA.y, fmaf(w2, dA.z, w3 * dA.w)));
    float aacc = (w0 + w1) + (w2 + w3);

    // ---- 4) chunk B: 2 survivals, scan seeded by carry ----
    const float gsB0 = fmaxf(gB.x, 0.f) * NLOG2E;
    const float gsB1 = fmaxf(gB.y, 0.f) * NLOG2E;
    const float eB0 = ex2_approx(gsB0 * (dB.y - dB.x));
    const float delB1 = (lane == 31) ? BOARDER : (ndB - dB.y);
    const float eB1 = ex2_approx(gsB1 * delB1);
    const float sB0 = eB0 + EPS, sB1 = eB1 + EPS;

    float inclB = sB0 * sB1;
    #pragma unroll
    for (int off = 1; off < 32; off <<= 1) {
        const float v = __shfl_up_sync(FULL, inclB, off);
        if (lane >= off) inclB *= v;
    }
    float exclB = __shfl_up_sync(FULL, inclB, 1);
    if (lane == 0) exclB = 1.0f;

    const float TB  = carry * exclB;
    const float wB0 = (1.0f - eB0) * TB;
    const float wB1 = (1.0f - eB1) * (TB * sB0);

    dacc = fmaf(wB0, dB.x, fmaf(wB1, dB.y, dacc));
    aacc += wB0 + wB1;

    // ---- 5) weights: direct coalesced stores ----
    float* __restrict__ wbase = out + (size_t)NRAYS * 5 + (size_t)ray * NSAMP;
    __stcs((float4*)wbase + lane, make_float4(w0, w1, w2, w3));
    __stcs((float2*)(wbase + 128) + lane, make_float2(wB0, wB1));

    // ---- 6) rgb consume: lane reads its OWN samples from smem ----
    asm volatile("cp.async.wait_group 0;\n" ::: "memory");
    __syncwarp();

    const float* rr = &srgb[wid][0];
    // samples 4l..4l+3 -> floats 12l..12l+11 (16B aligned)
    const float4 rA0 = *(const float4*)(rr + 12 * lane);      // r0 g0 b0 r1
    const float4 rA1 = *(const float4*)(rr + 12 * lane + 4);  // g1 b1 r2 g2
    const float4 rA2 = *(const float4*)(rr + 12 * lane + 8);  // b2 r3 g3 b3
    // samples 128+2l, 128+2l+1 -> floats 384+6l..+5 (8B aligned)
    const float2 rB0 = *(const float2*)(rr + 384 + 6 * lane);     // r0 g0
    const float2 rB1 = *(const float2*)(rr + 384 + 6 * lane + 2); // b0 r1
    const float2 rB2 = *(const float2*)(rr + 384 + 6 * lane + 4); // g1 b1

    float c0, c1, c2;
    c0 = fmaf(w0, sigmoid_fast(rA0.x),
         fmaf(w1, sigmoid_fast(rA0.w),
         fmaf(w2, sigmoid_fast(rA1.z),
              w3 * sigmoid_fast(rA2.y))));
    c1 = fmaf(w0, sigmoid_fast(rA0.y),
         fmaf(w1, sigmoid_fast(rA1.x),
         fmaf(w2, sigmoid_fast(rA1.w),
              w3 * sigmoid_fast(rA2.z))));
    c2 = fmaf(w0, sigmoid_fast(rA0.z),
         fmaf(w1, sigmoid_fast(rA1.y),
         fmaf(w2, sigmoid_fast(rA2.x),
              w3 * sigmoid_fast(rA2.w))));
    c0 = fmaf(wB0, sigmoid_fast(rB0.x), fmaf(wB1, sigmoid_fast(rB1.y), c0));
    c1 = fmaf(wB0, sigmoid_fast(rB0.y), fmaf(wB1, sigmoid_fast(rB2.x), c1));
    c2 = fmaf(wB0, sigmoid_fast(rB1.x), fmaf(wB1, sigmoid_fast(rB2.y), c2));

    // ---- 7) warp reduction + per-ray outputs ----
    #pragma unroll
    for (int off = 16; off > 0; off >>= 1) {
        c0   += __shfl_down_sync(FULL, c0,   off);
        c1   += __shfl_down_sync(FULL, c1,   off);
        c2   += __shfl_down_sync(FULL, c2,   off);
        dacc += __shfl_down_sync(FULL, dacc, off);
        aacc += __shfl_down_sync(FULL, aacc, off);
    }
    if (lane == 0) {
        out[3 * ray + 0] = c0;
        out[3 * ray + 1] = c1;
        out[3 * ray + 2] = c2;
        out[(size_t)NRAYS * 3 + ray] = dacc;
        out[(size_t)NRAYS * 4 + ray] = aacc;
    }
}

extern "C" void kernel_launch(void* const* d_in, const int* in_sizes, int n_in,
                              void* d_out, int out_size)
{
    const float* depth = (const float*)d_in[0];
    const float* rgb   = (const float*)d_in[1];
    const float* sigma = (const float*)d_in[2];
    float* out = (float*)d_out;

    const int threads = 32 * WPB;               // 256
    const int blocks  = NRAYS / WPB;            // 8192
    volrend_kernel<<<blocks, threads>>>(depth, rgb, sigma, out);
}